// round 12
// baseline (speedup 1.0000x reference)
#include <cuda_runtime.h>
#include <cuda_bf16.h>

#define CROP   7
#define NCELL  49
#define CCH    256     // channels
#define BASE_H 256     // level-2 feature H (=W)

__global__ __launch_bounds__(256, 5)
void roi_align_kernel(const float* __restrict__ f2,
                      const float* __restrict__ f3,
                      const float* __restrict__ f4,
                      const float* __restrict__ f5,
                      const float* __restrict__ boxes,
                      float* __restrict__ out,
                      int N)
{
    const int bn  = blockIdx.x;           // box id in [0, B*N)
    const int b   = bn / N;
    const int tid = threadIdx.x;

    // ---- per-row / per-col sampling tables (+ precombined offsets) ----
    __shared__ float s_ky[CROP][2];
    __shared__ float s_kx[CROP][2];
    __shared__ int   s_yoff[CROP][2];   // yi * Wl * CCH
    __shared__ int   s_xoff[CROP][2];   // xi * CCH
    __shared__ const float* s_fb;       // level base pointer for this image

    if (tid < 2 * CROP) {
        const float* bx = boxes + (size_t)bn * 4;
        float by0 = bx[0], bx0 = bx[1], by1 = bx[2], bx1 = bx[3];
        float bh = by1 - by0;
        float bw = bx1 - bx0;

        // level assignment: floor(log2(sqrt(h*w)/224)) + 4, clipped to [2,5]
        float lev_f = floorf(log2f(sqrtf(bh * bw) / 224.0f)) + 4.0f;
        lev_f = fminf(fmaxf(lev_f, 2.0f), 5.0f);
        int   lev  = (int)lev_f;
        int   lev0 = lev - 2;

        float inv_scale = exp2f(-(float)lev);   // exact (power of two)
        float y0b = by0 * inv_scale;
        float x0b = bx0 * inv_scale;
        bh *= inv_scale;
        bw *= inv_scale;

        int   Wl  = BASE_H >> lev0;             // H_l == W_l (square levels)
        float bnd = (float)Wl - 1.0f;

        int  i   = (tid < CROP) ? tid : (tid - CROP);
        bool isx = (tid >= CROP);
        // match JAX op order: (i + 0.5) * extent / CROP   (mul then div)
        float g  = (isx ? x0b : y0b) + ((float)i + 0.5f) * (isx ? bw : bh) / 7.0f;
        float c0 = fminf(fmaxf(floorf(g), 0.0f), bnd);
        float c1 = fminf(c0 + 1.0f, bnd);
        float l  = g - c0;                       // may be <0 or >1 (clipped), as in ref
        if (isx) {
            s_kx[i][0]   = 1.0f - l; s_kx[i][1] = l;
            s_xoff[i][0] = (int)c0 * CCH;
            s_xoff[i][1] = (int)c1 * CCH;
        } else {
            s_ky[i][0]   = 1.0f - l; s_ky[i][1] = l;
            s_yoff[i][0] = (int)c0 * Wl * CCH;
            s_yoff[i][1] = (int)c1 * Wl * CCH;
        }
        if (tid == 0) {
            const float* fp = (lev0 == 0) ? f2 : (lev0 == 1) ? f3
                            : (lev0 == 2) ? f4 : f5;
            s_fb = fp + (size_t)b * Wl * Wl * CCH;
        }
    }
    __syncthreads();

    const float* fb = s_fb;

    // ---- main loop: 8 cell-groups x 32 lanes; 2 float4 per corner row ----
    // MLP=8 LDG.128 per thread per iteration + L2 prefetch of the NEXT cell's
    // corner rows so next iteration's loads hit L2 instead of DRAM.
    const int group = tid >> 5;     // 0..7
    const int lane  = tid & 31;     // float4 index; covers lane and lane+32

    float* obase = out + (size_t)bn * NCELL * CCH;

    for (int cell = group; cell < NCELL; cell += 8) {
        int p = cell / CROP;
        int q = cell - p * CROP;

        int ra = s_yoff[p][0], rb = s_yoff[p][1];
        int ca = s_xoff[q][0], cb = s_xoff[q][1];

        const float4* r00 = (const float4*)(fb + ra + ca) + lane;
        const float4* r01 = (const float4*)(fb + ra + cb) + lane;
        const float4* r10 = (const float4*)(fb + rb + ca) + lane;
        const float4* r11 = (const float4*)(fb + rb + cb) + lane;

        // 8 independent loads, front-batched; +32 is an immediate offset
        float4 a00 = __ldg(r00);  float4 b00 = __ldg(r00 + 32);
        float4 a01 = __ldg(r01);  float4 b01 = __ldg(r01 + 32);
        float4 a10 = __ldg(r10);  float4 b10 = __ldg(r10 + 32);
        float4 a11 = __ldg(r11);  float4 b11 = __ldg(r11 + 32);

        // ---- prefetch next cell's 4 corner rows into L2 (registerless wrt
        // scoreboard; lanes 0,8,16,24 cover all 8x128B lines of each 1KB row)
        int next = cell + 8;
        if (next < NCELL && (lane & 7) == 0) {
            int p2 = next / CROP;
            int q2 = next - p2 * CROP;
            int ra2 = s_yoff[p2][0], rb2 = s_yoff[p2][1];
            int ca2 = s_xoff[q2][0], cb2 = s_xoff[q2][1];
            const char* n00 = (const char*)((const float4*)(fb + ra2 + ca2) + lane);
            const char* n01 = (const char*)((const float4*)(fb + ra2 + cb2) + lane);
            const char* n10 = (const char*)((const float4*)(fb + rb2 + ca2) + lane);
            const char* n11 = (const char*)((const float4*)(fb + rb2 + cb2) + lane);
            asm volatile("prefetch.global.L2 [%0];"     :: "l"(n00));
            asm volatile("prefetch.global.L2 [%0+512];" :: "l"(n00));
            asm volatile("prefetch.global.L2 [%0];"     :: "l"(n01));
            asm volatile("prefetch.global.L2 [%0+512];" :: "l"(n01));
            asm volatile("prefetch.global.L2 [%0];"     :: "l"(n10));
            asm volatile("prefetch.global.L2 [%0+512];" :: "l"(n10));
            asm volatile("prefetch.global.L2 [%0];"     :: "l"(n11));
            asm volatile("prefetch.global.L2 [%0+512];" :: "l"(n11));
        }

        float ky0 = s_ky[p][0], ky1 = s_ky[p][1];
        float kx0 = s_kx[q][0], kx1 = s_kx[q][1];
        float w00 = ky0 * kx0, w01 = ky0 * kx1;
        float w10 = ky1 * kx0, w11 = ky1 * kx1;

        float4 oa, ob;
        oa.x = w00 * a00.x + w01 * a01.x + w10 * a10.x + w11 * a11.x;
        oa.y = w00 * a00.y + w01 * a01.y + w10 * a10.y + w11 * a11.y;
        oa.z = w00 * a00.z + w01 * a01.z + w10 * a10.z + w11 * a11.z;
        oa.w = w00 * a00.w + w01 * a01.w + w10 * a10.w + w11 * a11.w;
        ob.x = w00 * b00.x + w01 * b01.x + w10 * b10.x + w11 * b11.x;
        ob.y = w00 * b00.y + w01 * b01.y + w10 * b10.y + w11 * b11.y;
        ob.z = w00 * b00.z + w01 * b01.z + w10 * b10.z + w11 * b11.z;
        ob.w = w00 * b00.w + w01 * b01.w + w10 * b10.w + w11 * b11.w;

        float4* op = (float4*)(obase + (size_t)cell * CCH) + lane;
        op[0]  = oa;
        op[32] = ob;
    }
}

extern "C" void kernel_launch(void* const* d_in, const int* in_sizes, int n_in,
                              void* d_out, int out_size)
{
    const float* f2    = (const float*)d_in[0];
    const float* f3    = (const float*)d_in[1];
    const float* f4    = (const float*)d_in[2];
    const float* f5    = (const float*)d_in[3];
    const float* boxes = (const float*)d_in[4];
    float* out = (float*)d_out;

    int BN = in_sizes[4] / 4;                       // B * N boxes
    int B  = in_sizes[0] / (256 * 256 * 256);       // feat2 is [B,256,256,256]
    int N  = BN / B;

    roi_align_kernel<<<BN, 256>>>(f2, f3, f4, f5, boxes, out, N);
}

// round 13
// speedup vs baseline: 1.0856x; 1.0856x over previous
#include <cuda_runtime.h>
#include <cuda_bf16.h>

#define CROP   7
#define NCELL  49
#define CCH    256     // channels
#define BASE_H 256     // level-2 feature H (=W)

__global__ __launch_bounds__(256, 5)
void roi_align_kernel(const float* __restrict__ f2,
                      const float* __restrict__ f3,
                      const float* __restrict__ f4,
                      const float* __restrict__ f5,
                      const float* __restrict__ boxes,
                      float* __restrict__ out,
                      int N)
{
    const int bn  = blockIdx.x;           // box id in [0, B*N)
    const int b   = bn / N;
    const int tid = threadIdx.x;

    // ---- per-row / per-col sampling tables (+ precombined offsets) ----
    __shared__ float s_ky[CROP][2];
    __shared__ float s_kx[CROP][2];
    __shared__ int   s_yoff[CROP][2];   // yi * Wl * CCH
    __shared__ int   s_xoff[CROP][2];   // xi * CCH
    __shared__ const float* s_fb;       // level base pointer for this image

    if (tid < 2 * CROP) {
        const float* bx = boxes + (size_t)bn * 4;
        float by0 = bx[0], bx0 = bx[1], by1 = bx[2], bx1 = bx[3];
        float bh = by1 - by0;
        float bw = bx1 - bx0;

        // level assignment: floor(log2(sqrt(h*w)/224)) + 4, clipped to [2,5]
        float lev_f = floorf(log2f(sqrtf(bh * bw) / 224.0f)) + 4.0f;
        lev_f = fminf(fmaxf(lev_f, 2.0f), 5.0f);
        int   lev  = (int)lev_f;
        int   lev0 = lev - 2;

        float inv_scale = exp2f(-(float)lev);   // exact (power of two)
        float y0b = by0 * inv_scale;
        float x0b = bx0 * inv_scale;
        bh *= inv_scale;
        bw *= inv_scale;

        int   Wl  = BASE_H >> lev0;             // H_l == W_l (square levels)
        float bnd = (float)Wl - 1.0f;

        int  i   = (tid < CROP) ? tid : (tid - CROP);
        bool isx = (tid >= CROP);
        // match JAX op order: (i + 0.5) * extent / CROP   (mul then div)
        float g  = (isx ? x0b : y0b) + ((float)i + 0.5f) * (isx ? bw : bh) / 7.0f;
        float c0 = fminf(fmaxf(floorf(g), 0.0f), bnd);
        float c1 = fminf(c0 + 1.0f, bnd);
        float l  = g - c0;                       // may be <0 or >1 (clipped), as in ref
        if (isx) {
            s_kx[i][0]   = 1.0f - l; s_kx[i][1] = l;
            s_xoff[i][0] = (int)c0 * CCH;
            s_xoff[i][1] = (int)c1 * CCH;
        } else {
            s_ky[i][0]   = 1.0f - l; s_ky[i][1] = l;
            s_yoff[i][0] = (int)c0 * Wl * CCH;
            s_yoff[i][1] = (int)c1 * Wl * CCH;
        }
        if (tid == 0) {
            const float* fp = (lev0 == 0) ? f2 : (lev0 == 1) ? f3
                            : (lev0 == 2) ? f4 : f5;
            s_fb = fp + (size_t)b * Wl * Wl * CCH;
        }
    }
    __syncthreads();

    const float* fb = s_fb;

    // ---- main loop: 8 cell-groups x 32 lanes; 2 float4 per corner row ----
    // Each thread issues 8 independent LDG.128 per iteration (MLP=8),
    // via the non-coherent read-only path (features are never written).
    const int group = tid >> 5;     // 0..7
    const int lane  = tid & 31;     // float4 index; covers lane and lane+32

    float* obase = out + (size_t)bn * NCELL * CCH;

    for (int cell = group; cell < NCELL; cell += 8) {
        int p = cell / CROP;
        int q = cell - p * CROP;

        int ra = s_yoff[p][0], rb = s_yoff[p][1];
        int ca = s_xoff[q][0], cb = s_xoff[q][1];

        const float4* r00 = (const float4*)(fb + ra + ca) + lane;
        const float4* r01 = (const float4*)(fb + ra + cb) + lane;
        const float4* r10 = (const float4*)(fb + rb + ca) + lane;
        const float4* r11 = (const float4*)(fb + rb + cb) + lane;

        // 8 independent loads, front-batched; +32 is an immediate offset
        float4 a00 = __ldg(r00);  float4 b00 = __ldg(r00 + 32);
        float4 a01 = __ldg(r01);  float4 b01 = __ldg(r01 + 32);
        float4 a10 = __ldg(r10);  float4 b10 = __ldg(r10 + 32);
        float4 a11 = __ldg(r11);  float4 b11 = __ldg(r11 + 32);

        float ky0 = s_ky[p][0], ky1 = s_ky[p][1];
        float kx0 = s_kx[q][0], kx1 = s_kx[q][1];
        float w00 = ky0 * kx0, w01 = ky0 * kx1;
        float w10 = ky1 * kx0, w11 = ky1 * kx1;

        float4 oa, ob;
        oa.x = w00 * a00.x + w01 * a01.x + w10 * a10.x + w11 * a11.x;
        oa.y = w00 * a00.y + w01 * a01.y + w10 * a10.y + w11 * a11.y;
        oa.z = w00 * a00.z + w01 * a01.z + w10 * a10.z + w11 * a11.z;
        oa.w = w00 * a00.w + w01 * a01.w + w10 * a10.w + w11 * a11.w;
        ob.x = w00 * b00.x + w01 * b01.x + w10 * b10.x + w11 * b11.x;
        ob.y = w00 * b00.y + w01 * b01.y + w10 * b10.y + w11 * b11.y;
        ob.z = w00 * b00.z + w01 * b01.z + w10 * b10.z + w11 * b11.z;
        ob.w = w00 * b00.w + w01 * b01.w + w10 * b10.w + w11 * b11.w;

        float4* op = (float4*)(obase + (size_t)cell * CCH) + lane;
        op[0]  = oa;
        op[32] = ob;
    }
}

extern "C" void kernel_launch(void* const* d_in, const int* in_sizes, int n_in,
                              void* d_out, int out_size)
{
    const float* f2    = (const float*)d_in[0];
    const float* f3    = (const float*)d_in[1];
    const float* f4    = (const float*)d_in[2];
    const float* f5    = (const float*)d_in[3];
    const float* boxes = (const float*)d_in[4];
    float* out = (float*)d_out;

    int BN = in_sizes[4] / 4;                       // B * N boxes
    int B  = in_sizes[0] / (256 * 256 * 256);       // feat2 is [B,256,256,256]
    int N  = BN / B;

    // Maximize L1D capacity: kernel uses only 232 B of smem, so request the
    // minimum shared-memory carveout (idempotent host-side attribute; not a
    // stream operation, safe under graph capture).
    static bool carveout_set = false;
    if (!carveout_set) {
        cudaFuncSetAttribute(roi_align_kernel,
                             cudaFuncAttributePreferredSharedMemoryCarveout,
                             0 /* percent smem -> max L1 */);
        carveout_set = true;
    }

    roi_align_kernel<<<BN, 256>>>(f2, f3, f4, f5, boxes, out, N);
}

// round 14
// speedup vs baseline: 1.0917x; 1.0057x over previous
#include <cuda_runtime.h>
#include <cuda_bf16.h>

#define CROP   7
#define NCELL  49
#define CCH    256     // channels
#define BASE_H 256     // level-2 feature H (=W)

// 256-bit global load: v8.f32 (Blackwell sm_100+)
__device__ __forceinline__ void ldg256(const float* p, float* v) {
    asm("ld.global.v8.f32 {%0,%1,%2,%3,%4,%5,%6,%7}, [%8];"
        : "=f"(v[0]), "=f"(v[1]), "=f"(v[2]), "=f"(v[3]),
          "=f"(v[4]), "=f"(v[5]), "=f"(v[6]), "=f"(v[7])
        : "l"(p));
}

// 256-bit global store
__device__ __forceinline__ void stg256(float* p, const float* v) {
    asm volatile("st.global.v8.f32 [%0], {%1,%2,%3,%4,%5,%6,%7,%8};"
        :: "l"(p),
           "f"(v[0]), "f"(v[1]), "f"(v[2]), "f"(v[3]),
           "f"(v[4]), "f"(v[5]), "f"(v[6]), "f"(v[7])
        : "memory");
}

__global__ __launch_bounds__(256, 5)
void roi_align_kernel(const float* __restrict__ f2,
                      const float* __restrict__ f3,
                      const float* __restrict__ f4,
                      const float* __restrict__ f5,
                      const float* __restrict__ boxes,
                      float* __restrict__ out,
                      int N)
{
    const int bn  = blockIdx.x;           // box id in [0, B*N)
    const int b   = bn / N;
    const int tid = threadIdx.x;

    // ---- per-row / per-col sampling tables (+ precombined offsets) ----
    __shared__ float s_ky[CROP][2];
    __shared__ float s_kx[CROP][2];
    __shared__ int   s_yoff[CROP][2];   // yi * Wl * CCH
    __shared__ int   s_xoff[CROP][2];   // xi * CCH
    __shared__ const float* s_fb;       // level base pointer for this image

    if (tid < 2 * CROP) {
        const float* bx = boxes + (size_t)bn * 4;
        float by0 = bx[0], bx0 = bx[1], by1 = bx[2], bx1 = bx[3];
        float bh = by1 - by0;
        float bw = bx1 - bx0;

        // level assignment: floor(log2(sqrt(h*w)/224)) + 4, clipped to [2,5]
        float lev_f = floorf(log2f(sqrtf(bh * bw) / 224.0f)) + 4.0f;
        lev_f = fminf(fmaxf(lev_f, 2.0f), 5.0f);
        int   lev  = (int)lev_f;
        int   lev0 = lev - 2;

        float inv_scale = exp2f(-(float)lev);   // exact (power of two)
        float y0b = by0 * inv_scale;
        float x0b = bx0 * inv_scale;
        bh *= inv_scale;
        bw *= inv_scale;

        int   Wl  = BASE_H >> lev0;             // H_l == W_l (square levels)
        float bnd = (float)Wl - 1.0f;

        int  i   = (tid < CROP) ? tid : (tid - CROP);
        bool isx = (tid >= CROP);
        // match JAX op order: (i + 0.5) * extent / CROP   (mul then div)
        float g  = (isx ? x0b : y0b) + ((float)i + 0.5f) * (isx ? bw : bh) / 7.0f;
        float c0 = fminf(fmaxf(floorf(g), 0.0f), bnd);
        float c1 = fminf(c0 + 1.0f, bnd);
        float l  = g - c0;                       // may be <0 or >1 (clipped), as in ref
        if (isx) {
            s_kx[i][0]   = 1.0f - l; s_kx[i][1] = l;
            s_xoff[i][0] = (int)c0 * CCH;
            s_xoff[i][1] = (int)c1 * CCH;
        } else {
            s_ky[i][0]   = 1.0f - l; s_ky[i][1] = l;
            s_yoff[i][0] = (int)c0 * Wl * CCH;
            s_yoff[i][1] = (int)c1 * Wl * CCH;
        }
        if (tid == 0) {
            const float* fp = (lev0 == 0) ? f2 : (lev0 == 1) ? f3
                            : (lev0 == 2) ? f4 : f5;
            s_fb = fp + (size_t)b * Wl * Wl * CCH;
        }
    }
    __syncthreads();

    const float* fb = s_fb;

    // ---- main loop: 8 cell-groups x 32 lanes; 256-bit accesses ----
    // Each lane owns one 32B chunk of the 1KB row: 4 x LDG.256 + 1 x STG.256
    // per cell (half the instructions of the float4 version, same bytes).
    const int group = tid >> 5;     // 0..7
    const int lane  = tid & 31;     // 32B-chunk index within the 256-ch row
    const int loff  = lane * 8;     // float offset of this lane's chunk

    float* obase = out + (size_t)bn * NCELL * CCH;

    for (int cell = group; cell < NCELL; cell += 8) {
        int p = cell / CROP;
        int q = cell - p * CROP;

        int ra = s_yoff[p][0], rb = s_yoff[p][1];
        int ca = s_xoff[q][0], cb = s_xoff[q][1];

        // 4 independent 256-bit loads, front-batched
        float v00[8], v01[8], v10[8], v11[8];
        ldg256(fb + ra + ca + loff, v00);
        ldg256(fb + ra + cb + loff, v01);
        ldg256(fb + rb + ca + loff, v10);
        ldg256(fb + rb + cb + loff, v11);

        float ky0 = s_ky[p][0], ky1 = s_ky[p][1];
        float kx0 = s_kx[q][0], kx1 = s_kx[q][1];
        float w00 = ky0 * kx0, w01 = ky0 * kx1;
        float w10 = ky1 * kx0, w11 = ky1 * kx1;

        float o[8];
        #pragma unroll
        for (int j = 0; j < 8; j++)
            o[j] = w00 * v00[j] + w01 * v01[j] + w10 * v10[j] + w11 * v11[j];

        stg256(obase + (size_t)cell * CCH + loff, o);
    }
}

extern "C" void kernel_launch(void* const* d_in, const int* in_sizes, int n_in,
                              void* d_out, int out_size)
{
    const float* f2    = (const float*)d_in[0];
    const float* f3    = (const float*)d_in[1];
    const float* f4    = (const float*)d_in[2];
    const float* f5    = (const float*)d_in[3];
    const float* boxes = (const float*)d_in[4];
    float* out = (float*)d_out;

    int BN = in_sizes[4] / 4;                       // B * N boxes
    int B  = in_sizes[0] / (256 * 256 * 256);       // feat2 is [B,256,256,256]
    int N  = BN / B;

    // Maximize L1D capacity (kernel uses only 232 B of smem).
    static bool carveout_set = false;
    if (!carveout_set) {
        cudaFuncSetAttribute(roi_align_kernel,
                             cudaFuncAttributePreferredSharedMemoryCarveout,
                             0 /* percent smem -> max L1 */);
        carveout_set = true;
    }

    roi_align_kernel<<<BN, 256>>>(f2, f3, f4, f5, boxes, out, N);
}